// round 11
// baseline (speedup 1.0000x reference)
#include <cuda_runtime.h>
#include <math.h>

#define EPSG 0.1f

namespace {
constexpr int Bn = 2, Sn = 2048, Dn = 1024, Hn = 16, DKn = 64;
constexpr int Mn = Bn * Sn;
constexpr int VP = 72;
constexpr int PP = 68;
constexpr int ATT_SMEM_FLOATS = 2 * 4096 + 2 * 64 * VP + 128 * PP;
constexpr int ATT_SMEM_BYTES  = ATT_SMEM_FLOATS * 4;   // 104448
constexpr int TILE_FLOATS = 128 * 16;                  // 2048
constexpr int PAIR_FLOATS = 2 * TILE_FLOATS;           // 4096 (k32)
constexpr int ROWTILE_FLOATS = 64 * TILE_FLOATS;
constexpr int GEMM_SMEM_BYTES = 3 * PAIR_FLOATS * 2 * 4;  // 96KB
}

#define QSCALE 0.18033688011112042f
#define C2     57.70780163555852f

__device__ float g_xp[(size_t)Mn * Dn];
__device__ float g_wqkvp[(size_t)3 * Dn * Dn];
__device__ float g_wop[(size_t)Dn * Dn];
__device__ float g_att[(size_t)Mn * Dn];
__device__ float g_q[Bn * Hn * Sn * DKn];
__device__ float g_k[Bn * Hn * Sn * DKn];
__device__ float g_v[Bn * Hn * Sn * DKn];

__device__ __forceinline__ float guard_clamp(float t, float amin, float amax) {
    float lo = fmaxf(t - EPSG, amin);
    float hi = fminf(t + EPSG, amax);
    lo = fminf(lo, hi);
    return fmaxf(lo, fminf(t, hi));
}

__device__ __forceinline__ float f2tf(float x) {
    unsigned u;
    asm("cvt.rna.tf32.f32 %0, %1;" : "=r"(u) : "f"(x));
    return __uint_as_float(u);
}

__device__ __forceinline__ float ex2(float x) {
    float r;
    asm("ex2.approx.f32 %0, %1;" : "=f"(r) : "f"(x));
    return r;
}

__device__ __forceinline__ void mma_tf32(float c[4], const unsigned a[4],
                                         const unsigned b[2]) {
    asm volatile(
        "mma.sync.aligned.m16n8k8.row.col.f32.tf32.tf32.f32 "
        "{%0,%1,%2,%3}, {%4,%5,%6,%7}, {%8,%9}, {%0,%1,%2,%3};"
        : "+f"(c[0]), "+f"(c[1]), "+f"(c[2]), "+f"(c[3])
        : "r"(a[0]), "r"(a[1]), "r"(a[2]), "r"(a[3]), "r"(b[0]), "r"(b[1]));
}

__device__ __forceinline__ void cpa16(unsigned dst, const void* src) {
    asm volatile("cp.async.ca.shared.global [%0], [%1], 16;"
                 :: "r"(dst), "l"(src));
}

__device__ __forceinline__ int posq(int d) {
    return ((d >> 4) << 4) + ((d & 3) << 2) + ((d >> 2) & 3);
}
__device__ __forceinline__ int posv(int d) {
    return ((d >> 5) << 5) + ((d & 7) << 2) + ((d >> 3) & 3);
}
__device__ __forceinline__ int posk(int s, int d) {
    const int r = s & 63;
    const int sw = (r ^ (r >> 2)) & 3;
    return ((s >> 6) << 12) + ((d >> 4) << 10) + (r << 4) +
           (((d & 3) ^ sw) << 2) + ((d >> 2) & 3);
}

// ---------------------------------------------------------------------------
template <int DST>
__global__ __launch_bounds__(256) void prepass(const float* __restrict__ src)
{
    float* dst = (DST == 0) ? g_xp : (DST == 1 ? g_wqkvp : g_wop);
    const int m = blockIdx.x, t = threadIdx.x;
    const float4 v = ((const float4*)(src + (size_t)m * Dn))[t];
    const int ro = m & 127;
    const int sw = (ro ^ (ro >> 2)) & 3;
    float* p = dst + (size_t)(m >> 7) * ROWTILE_FLOATS + (t >> 2) * TILE_FLOATS
               + ro * 16 + (t & 3);
    p[((0 ^ sw) << 2)] = f2tf(v.x);
    p[((1 ^ sw) << 2)] = f2tf(v.y);
    p[((2 ^ sw) << 2)] = f2tf(v.z);
    p[((3 ^ sw) << 2)] = f2tf(v.w);
}

// ---------------------------------------------------------------------------
// tf32 GEMM: 6-stage (3 pair-buffers) k32-per-barrier pipeline.
// Per iteration: wait_group 1 + 1 sync + 64 MMAs + one 32KB pair prefetch.
// ---------------------------------------------------------------------------
template <int MODE>
__global__ __launch_bounds__(256, 2) void gemm_tf32(
    const float* __restrict__ bias,
    const float* __restrict__ akmin, const float* __restrict__ akmax,
    const float* __restrict__ avmin, const float* __restrict__ avmax,
    float* __restrict__ out)
{
    extern __shared__ float smem[];
    float* Sa = smem;                           // [3][4096]
    float* Sb = smem + 3 * PAIR_FLOATS;         // [3][4096]

    const float* At = ((MODE == 1) ? (const float*)g_att : (const float*)g_xp)
                      + (size_t)blockIdx.y * ROWTILE_FLOATS;
    const float* Bt = ((MODE == 1) ? (const float*)g_wop : (const float*)g_wqkvp)
                      + (size_t)blockIdx.x * ROWTILE_FLOATS;

    const int tid = threadIdx.x;
    const int lane = tid & 31, warp = tid >> 5;
    const int gid = lane >> 2, tig = lane & 3;
    const int wm = warp & 1, wn = warp >> 1;
    const int m0 = blockIdx.y * 128, n0 = blockIdx.x * 128;

    const unsigned sa_sh = (unsigned)__cvta_generic_to_shared(Sa);
    const unsigned sb_sh = (unsigned)__cvta_generic_to_shared(Sb);

    auto prefetch2 = [&](int j) {               // j = k32 index (0..31)
        if (j < 32) {
            const int pp = j % 3;
            const float* Ap = At + (size_t)j * PAIR_FLOATS;
            const float* Bp = Bt + (size_t)j * PAIR_FLOATS;
            const unsigned soff = (unsigned)(pp * PAIR_FLOATS * 4);
#pragma unroll
            for (int p = 0; p < 4; ++p) {
                const int q = (tid + p * 256) * 4;
                cpa16(sa_sh + soff + q * 4, Ap + q);
                cpa16(sb_sh + soff + q * 4, Bp + q);
            }
        }
        asm volatile("cp.async.commit_group;");
    };

    auto ldFrag = [&](const float* buf, int r) -> float4 {
        const int sw = (r ^ (r >> 2)) & 3;
        return *(const float4*)(buf + r * 16 + ((tig ^ sw) << 2));
    };

    float acc[4][4][4];
#pragma unroll
    for (int mi = 0; mi < 4; ++mi)
#pragma unroll
        for (int ni = 0; ni < 4; ++ni)
#pragma unroll
            for (int r = 0; r < 4; ++r) acc[mi][ni][r] = 0.f;

    auto computeChunk = [&](const float* Ab, const float* Bb) {
        float4 fb[4];
#pragma unroll
        for (int ni = 0; ni < 4; ++ni)
            fb[ni] = ldFrag(Bb, wn * 32 + ni * 8 + gid);
#pragma unroll
        for (int mi = 0; mi < 4; ++mi) {
            const int r0 = wm * 64 + mi * 16 + gid;
            float4 fa0 = ldFrag(Ab, r0);
            float4 fa1 = ldFrag(Ab, r0 + 8);
            unsigned a0[4] = {__float_as_uint(fa0.x), __float_as_uint(fa1.x),
                              __float_as_uint(fa0.y), __float_as_uint(fa1.y)};
            unsigned a1[4] = {__float_as_uint(fa0.z), __float_as_uint(fa1.z),
                              __float_as_uint(fa0.w), __float_as_uint(fa1.w)};
#pragma unroll
            for (int ni = 0; ni < 4; ++ni) {
                unsigned b0[2] = {__float_as_uint(fb[ni].x),
                                  __float_as_uint(fb[ni].y)};
                mma_tf32(acc[mi][ni], a0, b0);
            }
#pragma unroll
            for (int ni = 0; ni < 4; ++ni) {
                unsigned b1[2] = {__float_as_uint(fb[ni].z),
                                  __float_as_uint(fb[ni].w)};
                mma_tf32(acc[mi][ni], a1, b1);
            }
        }
    };

    prefetch2(0);
    prefetch2(1);

    for (int it2 = 0; it2 < 32; ++it2) {
        asm volatile("cp.async.wait_group 1;");
        __syncthreads();
        const int pp = it2 % 3;
        const float* Ab = Sa + pp * PAIR_FLOATS;
        const float* Bb = Sb + pp * PAIR_FLOATS;
        computeChunk(Ab, Bb);
        computeChunk(Ab + TILE_FLOATS, Bb + TILE_FLOATS);
        prefetch2(it2 + 2);   // writes pair (it2-1)%3: freed by this sync
    }

    // ---------------- epilogue ----------------
#pragma unroll
    for (int mi = 0; mi < 4; ++mi) {
        const int mt = m0 + wm * 64 + mi * 16 + gid;
#pragma unroll
        for (int ni = 0; ni < 4; ++ni) {
            const int n = n0 + wn * 32 + ni * 8 + tig * 2;
            const float b0 = bias[n], b1 = bias[n + 1];
            float v00 = acc[mi][ni][0] + b0, v01 = acc[mi][ni][1] + b1;
            float v10 = acc[mi][ni][2] + b0, v11 = acc[mi][ni][3] + b1;
            if (MODE == 1) {
                *(float2*)(out + (size_t)mt * Dn + n)       = make_float2(v00, v01);
                *(float2*)(out + (size_t)(mt + 8) * Dn + n) = make_float2(v10, v11);
            } else {
                const int which = n >> 10;
                const int h = (n >> 6) & (Hn - 1);
                const int c = n & (DKn - 1);
                const int b_ = mt >> 11;
                const int s0 = mt & (Sn - 1), s1 = (mt + 8) & (Sn - 1);
                const size_t bhb = (size_t)(b_ * Hn + h) * Sn * DKn;
                if (which == 0) {
                    float* q0 = g_q + bhb + (size_t)s0 * DKn;
                    float* q1 = g_q + bhb + (size_t)s1 * DKn;
                    q0[posq(c)]     = f2tf(v00 * QSCALE);
                    q0[posq(c + 1)] = f2tf(v01 * QSCALE);
                    q1[posq(c)]     = f2tf(v10 * QSCALE);
                    q1[posq(c + 1)] = f2tf(v11 * QSCALE);
                } else {
                    const float* amin = (which == 1) ? akmin : avmin;
                    const float* amax = (which == 1) ? akmax : avmax;
                    const int ai = ((b_ * Hn + h) << 6) + c;
                    const float mn0 = amin[ai], mn1 = amin[ai + 1];
                    const float mx0 = amax[ai], mx1 = amax[ai + 1];
                    v00 = f2tf(guard_clamp(v00, mn0, mx0));
                    v01 = f2tf(guard_clamp(v01, mn1, mx1));
                    v10 = f2tf(guard_clamp(v10, mn0, mx0));
                    v11 = f2tf(guard_clamp(v11, mn1, mx1));
                    if (which == 1) {
                        float* kb = g_k + bhb;
                        kb[posk(s0, c)]     = v00;
                        kb[posk(s0, c + 1)] = v01;
                        kb[posk(s1, c)]     = v10;
                        kb[posk(s1, c + 1)] = v11;
                    } else {
                        float* vb0 = g_v + bhb + (size_t)s0 * DKn;
                        float* vb1 = g_v + bhb + (size_t)s1 * DKn;
                        vb0[posv(c)]     = v00;
                        vb0[posv(c + 1)] = v01;
                        vb1[posv(c)]     = v10;
                        vb1[posv(c + 1)] = v11;
                    }
                }
            }
        }
    }
}

// ---------------------------------------------------------------------------
// Attention: fixed-stabilizer softmax; score accs init to -C2 (saves FADDs);
// P stored raw fp32 (MMA truncation to tf32; bias cancels in normalization).
// ---------------------------------------------------------------------------
__global__ __launch_bounds__(256, 2) void attn_mma()
{
    extern __shared__ float sm[];
    float* Ks = sm;
    float* Vs = sm + 2 * 4096;
    float* Ps = Vs + 2 * 64 * VP;

    const int tid = threadIdx.x;
    const int lane = tid & 31, w = tid >> 5;
    const int gid = lane >> 2, tig = lane & 3;
    const int bh = blockIdx.y, qt = blockIdx.x;
    const size_t base = (size_t)bh * Sn * DKn;

    const unsigned ks_sh = (unsigned)__cvta_generic_to_shared(Ks);
    const unsigned vs_sh = (unsigned)__cvta_generic_to_shared(Vs);

    unsigned qa[8][4];
    {
        const float4* q0 = (const float4*)(g_q + base +
                           (size_t)(qt * 128 + w * 16 + gid) * DKn);
        const float4* q1 = q0 + 2 * DKn;   // +8 rows
#pragma unroll
        for (int c = 0; c < 4; ++c) {
            float4 A0 = q0[c * 4 + tig];
            float4 A1 = q1[c * 4 + tig];
            qa[2 * c][0]     = __float_as_uint(A0.x);
            qa[2 * c][1]     = __float_as_uint(A1.x);
            qa[2 * c][2]     = __float_as_uint(A0.y);
            qa[2 * c][3]     = __float_as_uint(A1.y);
            qa[2 * c + 1][0] = __float_as_uint(A0.z);
            qa[2 * c + 1][1] = __float_as_uint(A1.z);
            qa[2 * c + 1][2] = __float_as_uint(A0.w);
            qa[2 * c + 1][3] = __float_as_uint(A1.w);
        }
    }

    float o[8][4];
#pragma unroll
    for (int nt = 0; nt < 8; ++nt)
#pragma unroll
        for (int r = 0; r < 4; ++r) o[nt][r] = 0.f;
    float psum0 = 0.f, psum1 = 0.f;

    auto prefetch = [&](int kt) {
        const int buf = kt & 1;
        const float* Kg = g_k + base + (size_t)kt * 4096;
        const float* Vg = g_v + base + (size_t)kt * 64 * DKn;
#pragma unroll
        for (int p = 0; p < 4; ++p) {
            int i = tid + p * 256;
            cpa16(ks_sh + (unsigned)((buf * 4096 + i * 4) * 4), Kg + i * 4);
            int row = i >> 4, q = (i & 15) * 4;
            cpa16(vs_sh + (unsigned)((buf * 64 * VP + row * VP + q) * 4),
                  Vg + row * DKn + q);
        }
        asm volatile("cp.async.commit_group;");
    };

    prefetch(0);

    for (int kt = 0; kt < Sn / 64; ++kt) {
        if (kt < Sn / 64 - 1) {
            prefetch(kt + 1);
            asm volatile("cp.async.wait_group 1;");
        } else {
            asm volatile("cp.async.wait_group 0;");
        }
        __syncthreads();

        const int buf = kt & 1;
        const float* Kb = Ks + buf * 4096;
        const float* Vb = Vs + buf * 64 * VP;

        float s[8][4];
#pragma unroll
        for (int nt = 0; nt < 8; ++nt)
#pragma unroll
            for (int r = 0; r < 4; ++r) s[nt][r] = -C2;   // fold stabilizer
#pragma unroll
        for (int c = 0; c < 4; ++c) {
            const float* Kc = Kb + c * 1024;
#pragma unroll
            for (int nt = 0; nt < 8; ++nt) {
                const int r = nt * 8 + gid;
                const int sw = (r ^ (r >> 2)) & 3;
                float4 kb = *(const float4*)(Kc + r * 16 + ((tig ^ sw) << 2));
                unsigned b0[2] = {__float_as_uint(kb.x), __float_as_uint(kb.y)};
                unsigned b1[2] = {__float_as_uint(kb.z), __float_as_uint(kb.w)};
                mma_tf32(s[nt], qa[2 * c], b0);
                mma_tf32(s[nt], qa[2 * c + 1], b1);
            }
        }

        // p = 2^s (s already shifted); store raw fp32 (HW truncates to tf32)
        {
            float* pr0 = Ps + (w * 16 + gid) * PP + tig * 2;
            float* pr1 = pr0 + 8 * PP;
#pragma unroll
            for (int nt = 0; nt < 8; ++nt) {
                float p0 = ex2(s[nt][0]);
                float p1 = ex2(s[nt][1]);
                float p2 = ex2(s[nt][2]);
                float p3 = ex2(s[nt][3]);
                psum0 += p0 + p1;
                psum1 += p2 + p3;
                *(float2*)(pr0 + nt * 8) = make_float2(p0, p1);
                *(float2*)(pr1 + nt * 8) = make_float2(p2, p3);
            }
        }
        __syncwarp();

        const float* Pw = Ps + w * 16 * PP;
#pragma unroll
        for (int ks = 0; ks < 8; ++ks) {
            unsigned a[4];
            a[0] = __float_as_uint(Pw[gid * PP + ks * 8 + tig]);
            a[1] = __float_as_uint(Pw[(gid + 8) * PP + ks * 8 + tig]);
            a[2] = __float_as_uint(Pw[gid * PP + ks * 8 + tig + 4]);
            a[3] = __float_as_uint(Pw[(gid + 8) * PP + ks * 8 + tig + 4]);
            const float* rA = Vb + (ks * 8 + tig) * VP;
            const float* rB = rA + 4 * VP;
            float4 vA = *(const float4*)(rA + 4 * gid);
            float4 vB = *(const float4*)(rA + 32 + 4 * gid);
            float4 vC = *(const float4*)(rB + 4 * gid);
            float4 vD = *(const float4*)(rB + 32 + 4 * gid);
#pragma unroll
            for (int e = 0; e < 4; ++e) {
                unsigned b0[2] = {__float_as_uint(((const float*)&vA)[e]),
                                  __float_as_uint(((const float*)&vC)[e])};
                mma_tf32(o[e], a, b0);
                unsigned b1[2] = {__float_as_uint(((const float*)&vB)[e]),
                                  __float_as_uint(((const float*)&vD)[e])};
                mma_tf32(o[4 + e], a, b1);
            }
        }
        __syncthreads();
    }

    psum0 += __shfl_xor_sync(0xffffffffu, psum0, 1);
    psum0 += __shfl_xor_sync(0xffffffffu, psum0, 2);
    psum1 += __shfl_xor_sync(0xffffffffu, psum1, 1);
    psum1 += __shfl_xor_sync(0xffffffffu, psum1, 2);

    const int b_ = bh >> 4, h = bh & (Hn - 1);
    const float inv0 = 1.0f / psum0, inv1 = 1.0f / psum1;
    const int mrow = b_ * Sn + qt * 128 + w * 16 + gid;
    auto stA = [&](int m, int D, float v) {
        const int ro = m & 127;
        const int sw = (ro ^ (ro >> 2)) & 3;
        g_att[(size_t)(m >> 7) * ROWTILE_FLOATS + (D >> 4) * TILE_FLOATS +
              ro * 16 + (((D & 3) ^ sw) << 2) + ((D >> 2) & 3)] = v;
    };
#pragma unroll
    for (int nt = 0; nt < 8; ++nt) {
        const int D = h * 64 + nt * 8 + tig * 2;
        stA(mrow,     D,     f2tf(o[nt][0] * inv0));
        stA(mrow,     D + 1, f2tf(o[nt][1] * inv0));
        stA(mrow + 8, D,     f2tf(o[nt][2] * inv1));
        stA(mrow + 8, D + 1, f2tf(o[nt][3] * inv1));
    }
}

extern "C" void kernel_launch(void* const* d_in, const int* in_sizes, int n_in,
                              void* d_out, int out_size)
{
    const float* x      = (const float*)d_in[0];
    const float* qkv_w  = (const float*)d_in[1];
    const float* qkv_b  = (const float*)d_in[2];
    const float* out_w  = (const float*)d_in[3];
    const float* out_b  = (const float*)d_in[4];
    const float* akmin  = (const float*)d_in[5];
    const float* akmax  = (const float*)d_in[6];
    const float* avmin  = (const float*)d_in[7];
    const float* avmax  = (const float*)d_in[8];
    float* out = (float*)d_out;

    prepass<0><<<Mn, 256>>>(x);
    prepass<1><<<3 * Dn, 256>>>(qkv_w);
    prepass<2><<<Dn, 256>>>(out_w);

    cudaFuncSetAttribute(gemm_tf32<0>,
                         cudaFuncAttributeMaxDynamicSharedMemorySize,
                         GEMM_SMEM_BYTES);
    cudaFuncSetAttribute(gemm_tf32<1>,
                         cudaFuncAttributeMaxDynamicSharedMemorySize,
                         GEMM_SMEM_BYTES);
    cudaFuncSetAttribute(attn_mma, cudaFuncAttributeMaxDynamicSharedMemorySize,
                         ATT_SMEM_BYTES);

    gemm_tf32<0><<<dim3(3 * Dn / 128, Mn / 128), 256, GEMM_SMEM_BYTES>>>(
        qkv_b, akmin, akmax, avmin, avmax, nullptr);

    attn_mma<<<dim3(Sn / 128, Bn * Hn), 256, ATT_SMEM_BYTES>>>();

    gemm_tf32<1><<<dim3(Dn / 128, Mn / 128), 256, GEMM_SMEM_BYTES>>>(
        out_b, nullptr, nullptr, nullptr, nullptr, out);
}

// round 14
// speedup vs baseline: 1.5186x; 1.5186x over previous
#include <cuda_runtime.h>
#include <cuda_fp16.h>
#include <math.h>

#define EPSG 0.1f

namespace {
constexpr int Bn = 2, Sn = 2048, Dn = 1024, Hn = 16, DKn = 64;
constexpr int Mn = Bn * Sn;
constexpr int VP = 72;
constexpr int PP = 68;
constexpr int CHUNK = 2048;              // float-slots per 128x(k32) fp16 chunk (8KB)
constexpr int RT16 = 32 * CHUNK;         // per 128-row tile, K=1024
constexpr int GEMM_SMEM_BYTES = 4 * 2 * CHUNK * 4;  // 4 stages x (A+B) = 64KB
constexpr int ATT_SMEM_FLOATS = 2 * CHUNK + 2 * 64 * VP + 128 * PP;  // 22016
constexpr int ATT_SMEM_BYTES  = ATT_SMEM_FLOATS * 4;                 // 88064
}

#define QSCALE 0.18033688011112042f   // (1/8)*log2(e)
#define C2     57.70780163555852f     // 40*log2(e)

// fp16 pair-images (each float slot = one half2)
__device__ float g_xp[(size_t)(Mn / 128) * RT16];
__device__ float g_wqkvp[(size_t)(3 * Dn / 128) * RT16];
__device__ float g_wop[(size_t)(Dn / 128) * RT16];
__device__ float g_att[(size_t)(Mn / 128) * RT16];
__device__ float g_q[(size_t)Bn * Hn * Sn * 32];   // fp16 pairs, frag-ready rows
__device__ float g_k[(size_t)Bn * Hn * Sn * 32];   // fp16 pairs, swizzled tile image
__device__ float g_v[(size_t)Bn * Hn * Sn * DKn];  // fp32 (PV stays tf32)

__device__ __forceinline__ float guard_clamp(float t, float amin, float amax) {
    float lo = fmaxf(t - EPSG, amin);
    float hi = fminf(t + EPSG, amax);
    lo = fminf(lo, hi);
    return fmaxf(lo, fminf(t, hi));
}

__device__ __forceinline__ float f2tf(float x) {
    unsigned u;
    asm("cvt.rna.tf32.f32 %0, %1;" : "=r"(u) : "f"(x));
    return __uint_as_float(u);
}

__device__ __forceinline__ float pack2h(float a, float b) {
    __half2 h = __floats2half2_rn(a, b);
    return __uint_as_float(*reinterpret_cast<unsigned*>(&h));
}

__device__ __forceinline__ float ex2(float x) {
    float r;
    asm("ex2.approx.f32 %0, %1;" : "=f"(r) : "f"(x));
    return r;
}

__device__ __forceinline__ void mma_f16(float c[4], const unsigned a[4],
                                        const unsigned b[2]) {
    asm volatile(
        "mma.sync.aligned.m16n8k16.row.col.f32.f16.f16.f32 "
        "{%0,%1,%2,%3}, {%4,%5,%6,%7}, {%8,%9}, {%0,%1,%2,%3};"
        : "+f"(c[0]), "+f"(c[1]), "+f"(c[2]), "+f"(c[3])
        : "r"(a[0]), "r"(a[1]), "r"(a[2]), "r"(a[3]), "r"(b[0]), "r"(b[1]));
}

__device__ __forceinline__ void mma_tf32(float c[4], const unsigned a[4],
                                         const unsigned b[2]) {
    asm volatile(
        "mma.sync.aligned.m16n8k8.row.col.f32.tf32.tf32.f32 "
        "{%0,%1,%2,%3}, {%4,%5,%6,%7}, {%8,%9}, {%0,%1,%2,%3};"
        : "+f"(c[0]), "+f"(c[1]), "+f"(c[2]), "+f"(c[3])
        : "r"(a[0]), "r"(a[1]), "r"(a[2]), "r"(a[3]), "r"(b[0]), "r"(b[1]));
}

__device__ __forceinline__ void cpa16(unsigned dst, const void* src) {
    asm volatile("cp.async.ca.shared.global [%0], [%1], 16;"
                 :: "r"(dst), "l"(src));
}

__device__ __forceinline__ int posv(int d) {           // V fp32 map (R10)
    return ((d >> 5) << 5) + ((d & 7) << 2) + ((d >> 3) & 3);
}

// ---------------------------------------------------------------------------
// Prepass: [rows x 1024] fp32 -> fp16 pair-image [m>>7][k>>5][128][16 slots],
// slot(j) = ((j&3)^sw)*4 + (j>>2), sw = (ro^(ro>>2))&3, pair j = (k>>1)&15.
// ---------------------------------------------------------------------------
template <int DST>
__global__ __launch_bounds__(256) void prepass(const float* __restrict__ src)
{
    float* dst = (DST == 0) ? g_xp : (DST == 1 ? g_wqkvp : g_wop);
    const int m = blockIdx.x, t = threadIdx.x;
    const float4 v = ((const float4*)(src + (size_t)m * Dn))[t];
    const int ro = m & 127;
    const int sw = (ro ^ (ro >> 2)) & 3;
    const int j0 = (2 * t) & 15;
    float* p = dst + (size_t)(m >> 7) * RT16 + (t >> 3) * CHUNK + ro * 16;
    p[(((j0 & 3) ^ sw) << 2) + (j0 >> 2)]             = pack2h(v.x, v.y);
    p[((((j0 + 1) & 3) ^ sw) << 2) + ((j0 + 1) >> 2)] = pack2h(v.z, v.w);
}

// ---------------------------------------------------------------------------
// fp16 GEMM (m16n8k16): 4-stage cp.async, 32 k32-iterations.
// MODE 0: A=g_xp, B=g_wqkvp, QKV epilogue. MODE 1: A=g_att, B=g_wop, proj.
// ---------------------------------------------------------------------------
template <int MODE>
__global__ __launch_bounds__(256, 2) void gemm_f16(
    const float* __restrict__ bias,
    const float* __restrict__ akmin, const float* __restrict__ akmax,
    const float* __restrict__ avmin, const float* __restrict__ avmax,
    float* __restrict__ out)
{
    extern __shared__ float smem[];
    float* Sa = smem;                       // [4][2048]
    float* Sb = smem + 4 * CHUNK;           // [4][2048]

    const float* At = ((MODE == 1) ? (const float*)g_att : (const float*)g_xp)
                      + (size_t)blockIdx.y * RT16;
    const float* Bt = ((MODE == 1) ? (const float*)g_wop : (const float*)g_wqkvp)
                      + (size_t)blockIdx.x * RT16;

    const int tid = threadIdx.x;
    const int lane = tid & 31, warp = tid >> 5;
    const int gid = lane >> 2, tig = lane & 3;
    const int wm = warp & 1, wn = warp >> 1;
    const int m0 = blockIdx.y * 128, n0 = blockIdx.x * 128;

    const unsigned sa_sh = (unsigned)__cvta_generic_to_shared(Sa);
    const unsigned sb_sh = (unsigned)__cvta_generic_to_shared(Sb);

    auto prefetch = [&](int it) {
        if (it < 32) {
            const int st = it & 3;
            const float* Ap = At + (size_t)it * CHUNK;
            const float* Bp = Bt + (size_t)it * CHUNK;
#pragma unroll
            for (int p = 0; p < 2; ++p) {
                const int j = (tid + p * 256) * 4;
                cpa16(sa_sh + (unsigned)((st * CHUNK + j) * 4), Ap + j);
                cpa16(sb_sh + (unsigned)((st * CHUNK + j) * 4), Bp + j);
            }
        }
        asm volatile("cp.async.commit_group;");
    };

    auto ldFrag = [&](const float* buf, int r) -> float4 {
        const int sw = (r ^ (r >> 2)) & 3;
        return *(const float4*)(buf + r * 16 + ((tig ^ sw) << 2));
    };

    float acc[4][4][4];
#pragma unroll
    for (int mi = 0; mi < 4; ++mi)
#pragma unroll
        for (int ni = 0; ni < 4; ++ni)
#pragma unroll
            for (int r = 0; r < 4; ++r) acc[mi][ni][r] = 0.f;

    prefetch(0); prefetch(1); prefetch(2);

    for (int it = 0; it < 32; ++it) {
        asm volatile("cp.async.wait_group 2;");
        __syncthreads();
        const float* Ab = Sa + (it & 3) * CHUNK;
        const float* Bb = Sb + (it & 3) * CHUNK;

        float4 fb[4];
#pragma unroll
        for (int ni = 0; ni < 4; ++ni)
            fb[ni] = ldFrag(Bb, wn * 32 + ni * 8 + gid);
#pragma unroll
        for (int mi = 0; mi < 4; ++mi) {
            const int r0 = wm * 64 + mi * 16 + gid;
            float4 fa0 = ldFrag(Ab, r0);
            float4 fa1 = ldFrag(Ab, r0 + 8);
            unsigned a0[4] = {__float_as_uint(fa0.x), __float_as_uint(fa1.x),
                              __float_as_uint(fa0.y), __float_as_uint(fa1.y)};
            unsigned a1[4] = {__float_as_uint(fa0.z), __float_as_uint(fa1.z),
                              __float_as_uint(fa0.w), __float_as_uint(fa1.w)};
#pragma unroll
            for (int ni = 0; ni < 4; ++ni) {
                unsigned b0[2] = {__float_as_uint(fb[ni].x),
                                  __float_as_uint(fb[ni].y)};
                mma_f16(acc[mi][ni], a0, b0);
            }
#pragma unroll
            for (int ni = 0; ni < 4; ++ni) {
                unsigned b1[2] = {__float_as_uint(fb[ni].z),
                                  __float_as_uint(fb[ni].w)};
                mma_f16(acc[mi][ni], a1, b1);
            }
        }
        prefetch(it + 3);
    }

    // ---------------- epilogue ----------------
#pragma unroll
    for (int mi = 0; mi < 4; ++mi) {
        const int mt = m0 + wm * 64 + mi * 16 + gid;
#pragma unroll
        for (int ni = 0; ni < 4; ++ni) {
            const int n = n0 + wn * 32 + ni * 8 + tig * 2;     // n even
            const float b0 = bias[n], b1 = bias[n + 1];
            float v00 = acc[mi][ni][0] + b0, v01 = acc[mi][ni][1] + b1;
            float v10 = acc[mi][ni][2] + b0, v11 = acc[mi][ni][3] + b1;
            if (MODE == 1) {
                *(float2*)(out + (size_t)mt * Dn + n)       = make_float2(v00, v01);
                *(float2*)(out + (size_t)(mt + 8) * Dn + n) = make_float2(v10, v11);
            } else {
                const int which = n >> 10;
                const int h = (n >> 6) & (Hn - 1);
                const int c = n & (DKn - 1);                   // even
                const int b_ = mt >> 11;
                const int s0 = mt & (Sn - 1), s1 = (mt + 8) & (Sn - 1);
                const int j = (c >> 1) & 15;
                if (which == 0) {
                    const size_t qb = ((size_t)(b_ * Hn + h) * Sn) * 32;
                    const int slot = ((c >> 5) << 4) + ((j & 3) << 2) + (j >> 2);
                    g_q[qb + (size_t)s0 * 32 + slot] =
                        pack2h(v00 * QSCALE, v01 * QSCALE);
                    g_q[qb + (size_t)s1 * 32 + slot] =
                        pack2h(v10 * QSCALE, v11 * QSCALE);
                } else {
                    const float* amin = (which == 1) ? akmin : avmin;
                    const float* amax = (which == 1) ? akmax : avmax;
                    const int ai = ((b_ * Hn + h) << 6) + c;
                    const float mn0 = amin[ai], mn1 = amin[ai + 1];
                    const float mx0 = amax[ai], mx1 = amax[ai + 1];
                    v00 = guard_clamp(v00, mn0, mx0);
                    v01 = guard_clamp(v01, mn1, mx1);
                    v10 = guard_clamp(v10, mn0, mx0);
                    v11 = guard_clamp(v11, mn1, mx1);
                    if (which == 1) {
                        const size_t kb = ((size_t)(b_ * Hn + h) * Sn) * 32;
                        const int r0_ = s0 & 63, r1_ = s1 & 63;
                        const int sw0 = (r0_ ^ (r0_ >> 2)) & 3;
                        const int sw1 = (r1_ ^ (r1_ >> 2)) & 3;
                        g_k[kb + (s0 >> 6) * 2048 + (c >> 5) * 1024 + r0_ * 16 +
                            (((j & 3) ^ sw0) << 2) + (j >> 2)] = pack2h(v00, v01);
                        g_k[kb + (s1 >> 6) * 2048 + (c >> 5) * 1024 + r1_ * 16 +
                            (((j & 3) ^ sw1) << 2) + (j >> 2)] = pack2h(v10, v11);
                    } else {
                        float* vb0 = g_v + ((size_t)(b_ * Hn + h) * Sn + s0) * DKn;
                        float* vb1 = g_v + ((size_t)(b_ * Hn + h) * Sn + s1) * DKn;
                        vb0[posv(c)]     = f2tf(v00);
                        vb0[posv(c + 1)] = f2tf(v01);
                        vb1[posv(c)]     = f2tf(v10);
                        vb1[posv(c + 1)] = f2tf(v11);
                    }
                }
            }
        }
    }
}

// ---------------------------------------------------------------------------
// Attention: QK in fp16 m16n8k16 (K image, Q frag-ready), softmax + PV = R10.
// ---------------------------------------------------------------------------
__global__ __launch_bounds__(256, 2) void attn_mma()
{
    extern __shared__ float sm[];
    float* Ks = sm;                       // [2][2048] fp16 pairs
    float* Vs = sm + 2 * CHUNK;           // [2][64][VP] fp32
    float* Ps = Vs + 2 * 64 * VP;         // [128][PP] fp32

    const int tid = threadIdx.x;
    const int lane = tid & 31, w = tid >> 5;
    const int gid = lane >> 2, tig = lane & 3;
    const int bh = blockIdx.y, qt = blockIdx.x;
    const size_t base32 = (size_t)bh * Sn * 32;
    const size_t base64 = (size_t)bh * Sn * DKn;

    const unsigned ks_sh = (unsigned)__cvta_generic_to_shared(Ks);
    const unsigned vs_sh = (unsigned)__cvta_generic_to_shared(Vs);

    unsigned qa[4][4];
    {
        const float4* q0 = (const float4*)(g_q + base32 +
                           (size_t)(qt * 128 + w * 16 + gid) * 32);
        const float4* q1 = q0 + 64;        // +8 rows (8*32 floats / 4)
#pragma unroll
        for (int c = 0; c < 2; ++c) {
            float4 A0 = q0[c * 4 + tig];
            float4 A1 = q1[c * 4 + tig];
            qa[2 * c][0]     = __float_as_uint(A0.x);
            qa[2 * c][1]     = __float_as_uint(A1.x);
            qa[2 * c][2]     = __float_as_uint(A0.y);
            qa[2 * c][3]     = __float_as_uint(A1.y);
            qa[2 * c + 1][0] = __float_as_uint(A0.z);
            qa[2 * c + 1][1] = __float_as_uint(A1.z);
            qa[2 * c + 1][2] = __float_as_uint(A0.w);
            qa[2 * c + 1][3] = __float_as_uint(A1.w);
        }
    }

    float o[8][4];
#pragma unroll
    for (int nt = 0; nt < 8; ++nt)
#pragma unroll
        for (int r = 0; r < 4; ++r) o[nt][r] = 0.f;
    float psum0 = 0.f, psum1 = 0.f;

    auto prefetch = [&](int kt) {
        const int buf = kt & 1;
        const float* Kg = g_k + base32 + (size_t)kt * 2048;  // linear fp16 tile
        const float* Vg = g_v + base64 + (size_t)kt * 64 * DKn;
#pragma unroll
        for (int p = 0; p < 2; ++p) {
            int i = tid + p * 256;        // 512 float4 slots of K
            cpa16(ks_sh + (unsigned)((buf * CHUNK + i * 4) * 4), Kg + i * 4);
        }
#pragma unroll
        for (int p = 0; p < 4; ++p) {
            int i = tid + p * 256;
            int row = i >> 4, q = (i & 15) * 4;
            cpa16(vs_sh + (unsigned)((buf * 64 * VP + row * VP + q) * 4),
                  Vg + row * DKn + q);
        }
        asm volatile("cp.async.commit_group;");
    };

    prefetch(0);

    for (int kt = 0; kt < Sn / 64; ++kt) {
        if (kt < Sn / 64 - 1) {
            prefetch(kt + 1);
            asm volatile("cp.async.wait_group 1;");
        } else {
            asm volatile("cp.async.wait_group 0;");
        }
        __syncthreads();

        const int buf = kt & 1;
        const float* Kb = Ks + buf * CHUNK;
        const float* Vb = Vs + buf * 64 * VP;

        // S = Q . K^T  (fp16: 32 MMA, 16 LDS.128)
        float s[8][4];
#pragma unroll
        for (int nt = 0; nt < 8; ++nt)
#pragma unroll
            for (int r = 0; r < 4; ++r) s[nt][r] = 0.f;
#pragma unroll
        for (int c = 0; c < 2; ++c) {
            const float* Kc = Kb + c * 1024;
#pragma unroll
            for (int nt = 0; nt < 8; ++nt) {
                const int r = nt * 8 + gid;
                const int sw = (r ^ (r >> 2)) & 3;
                float4 kb = *(const float4*)(Kc + r * 16 + ((tig ^ sw) << 2));
                unsigned b0[2] = {__float_as_uint(kb.x), __float_as_uint(kb.y)};
                unsigned b1[2] = {__float_as_uint(kb.z), __float_as_uint(kb.w)};
                mma_f16(s[nt], qa[2 * c], b0);
                mma_f16(s[nt], qa[2 * c + 1], b1);
            }
        }

        // fixed-stabilizer softmax (R10)
        {
            float* pr0 = Ps + (w * 16 + gid) * PP + tig * 2;
            float* pr1 = pr0 + 8 * PP;
#pragma unroll
            for (int nt = 0; nt < 8; ++nt) {
                float p0 = ex2(s[nt][0] - C2);
                float p1 = ex2(s[nt][1] - C2);
                float p2 = ex2(s[nt][2] - C2);
                float p3 = ex2(s[nt][3] - C2);
                psum0 += p0 + p1;
                psum1 += p2 + p3;
                *(float2*)(pr0 + nt * 8) = make_float2(f2tf(p0), f2tf(p1));
                *(float2*)(pr1 + nt * 8) = make_float2(f2tf(p2), f2tf(p3));
            }
        }
        __syncwarp();

        // O += P . V  (tf32, R10 verbatim)
        const float* Pw = Ps + w * 16 * PP;
#pragma unroll
        for (int ks = 0; ks < 8; ++ks) {
            unsigned a[4];
            a[0] = __float_as_uint(Pw[gid * PP + ks * 8 + tig]);
            a[1] = __float_as_uint(Pw[(gid + 8) * PP + ks * 8 + tig]);
            a[2] = __float_as_uint(Pw[gid * PP + ks * 8 + tig + 4]);
            a[3] = __float_as_uint(Pw[(gid + 8) * PP + ks * 8 + tig + 4]);
            const float* rA = Vb + (ks * 8 + tig) * VP;
            const float* rB = rA + 4 * VP;
            float4 vA = *(const float4*)(rA + 4 * gid);
            float4 vB = *(const float4*)(rA + 32 + 4 * gid);
            float4 vC = *(const float4*)(rB + 4 * gid);
            float4 vD = *(const float4*)(rB + 32 + 4 * gid);
#pragma unroll
            for (int e = 0; e < 4; ++e) {
                unsigned b0[2] = {__float_as_uint(((const float*)&vA)[e]),
                                  __float_as_uint(((const float*)&vC)[e])};
                mma_tf32(o[e], a, b0);
                unsigned b1[2] = {__float_as_uint(((const float*)&vB)[e]),
                                  __float_as_uint(((const float*)&vD)[e])};
                mma_tf32(o[4 + e], a, b1);
            }
        }
        __syncthreads();
    }

    psum0 += __shfl_xor_sync(0xffffffffu, psum0, 1);
    psum0 += __shfl_xor_sync(0xffffffffu, psum0, 2);
    psum1 += __shfl_xor_sync(0xffffffffu, psum1, 1);
    psum1 += __shfl_xor_sync(0xffffffffu, psum1, 2);

    const int b_ = bh >> 4, h = bh & (Hn - 1);
    const float inv0 = 1.0f / psum0, inv1 = 1.0f / psum1;
    const int mrow = b_ * Sn + qt * 128 + w * 16 + gid;
    auto stA = [&](int m, int D, float v2) {
        const int ro = m & 127;
        const int sw = (ro ^ (ro >> 2)) & 3;
        const int j = (D >> 1) & 15;
        g_att[(size_t)(m >> 7) * RT16 + (D >> 5) * CHUNK + ro * 16 +
              (((j & 3) ^ sw) << 2) + (j >> 2)] = v2;
    };
#pragma unroll
    for (int nt = 0; nt < 8; ++nt) {
        const int D = h * 64 + nt * 8 + tig * 2;   // even
        stA(mrow,     D, pack2h(o[nt][0] * inv0, o[nt][1] * inv0));
        stA(mrow + 8, D, pack2h(o[nt][2] * inv1, o[nt][3] * inv1));
    }
}

extern "C" void kernel_launch(void* const* d_in, const int* in_sizes, int n_in,
                              void* d_out, int out_size)
{
    const float* x      = (const float*)d_in[0];
    const float* qkv_w  = (const float*)d_in[1];
    const float* qkv_b  = (const float*)d_in[2];
    const float* out_w  = (const float*)d_in[3];
    const float* out_b  = (const float*)d_in[4];
    const float* akmin  = (const float*)d_in[5];
    const float* akmax  = (const float*)d_in[6];
    const float* avmin  = (const float*)d_in[7];
    const float* avmax  = (const float*)d_in[8];
    float* out = (float*)d_out;

    prepass<0><<<Mn, 256>>>(x);
    prepass<1><<<3 * Dn, 256>>>(qkv_w);
    prepass<2><<<Dn, 256>>>(out_w);

    cudaFuncSetAttribute(gemm_f16<0>,
                         cudaFuncAttributeMaxDynamicSharedMemorySize,
                         GEMM_SMEM_BYTES);
    cudaFuncSetAttribute(gemm_f16<1>,
                         cudaFuncAttributeMaxDynamicSharedMemorySize,
                         GEMM_SMEM_BYTES);
    cudaFuncSetAttribute(attn_mma, cudaFuncAttributeMaxDynamicSharedMemorySize,
                         ATT_SMEM_BYTES);

    gemm_f16<0><<<dim3(3 * Dn / 128, Mn / 128), 256, GEMM_SMEM_BYTES>>>(
        qkv_b, akmin, akmax, avmin, avmax, nullptr);

    attn_mma<<<dim3(Sn / 128, Bn * Hn), 256, ATT_SMEM_BYTES>>>();

    gemm_f16<1><<<dim3(Dn / 128, Mn / 128), 256, GEMM_SMEM_BYTES>>>(
        out_b, nullptr, nullptr, nullptr, nullptr, out);
}